// round 5
// baseline (speedup 1.0000x reference)
#include <cuda_runtime.h>
#include <cuda_bf16.h>
#include <math.h>

// Problem constants
#define NB   128
#define NS   2048
#define NM   50
#define NDK  64
#define NDV  128
#define NK   5
#define NDS  50
#define NQ   1001
#define NPOS (NB*NS)   // 262144

typedef unsigned long long ull;

// ---- packed f32x2 helpers (bit-identical per lane to scalar fp32) ----
__device__ __forceinline__ ull ffma2(ull a, ull b, ull c) {
    ull d;
    asm("fma.rn.f32x2 %0, %1, %2, %3;" : "=l"(d) : "l"(a), "l"(b), "l"(c));
    return d;
}
__device__ __forceinline__ ull fadd2(ull a, ull b) {
    ull d;
    asm("add.rn.f32x2 %0, %1, %2;" : "=l"(d) : "l"(a), "l"(b));
    return d;
}
__device__ __forceinline__ ull pack2(float lo, float hi) {
    ull r; asm("mov.b64 %0, {%1,%2};" : "=l"(r) : "f"(lo), "f"(hi)); return r;
}
__device__ __forceinline__ float2 unpack2(ull v) {
    float2 f; asm("mov.b64 {%0,%1}, %2;" : "=f"(f.x), "=f"(f.y) : "l"(v)); return f;
}

// -------- scratch (__device__ globals; no runtime allocation) --------
__device__ float  g_attn [NQ * 64];            // softmax(q_e @ key_mem^T); [50,64) ZERO
__device__ float  g_sumq [NQ * 64];            // q_e @ summary_w[128:192], stride 64
__device__ float  g_alpha[NQ];
__device__ float  g_beta [NQ * 4];
__device__ float2 g_ea   [NQ * NK * NDV];      // (.x=erase sigmoid, .y=add tanh)
__device__ float  g_reads[(long)NB * NS * NDV];// 134 MB

// ======================= Phase A1: per-question tables =======================
__global__ void build_q_tables(const float* __restrict__ qe_w,
                               const float* __restrict__ key_mem,
                               const float* __restrict__ sum_w,
                               const float* __restrict__ alpha_w,
                               const float* __restrict__ alpha_b,
                               const float* __restrict__ beta_w,
                               const float* __restrict__ beta_b) {
    int q = blockIdx.x;
    int tid = threadIdx.x;           // 64 threads
    __shared__ float qe[64];
    __shared__ float lg[NM];
    qe[tid] = qe_w[q * 64 + tid];
    __syncthreads();

    if (tid < NM) {
        float a = 0.f, s = 0.f;
        #pragma unroll
        for (int k = 0; k < 64; k++) {
            float qk = qe[k];
            a = fmaf(qk, key_mem[tid * 64 + k], a);
            s = fmaf(qk, sum_w[(128 + k) * NDS + tid], s);
        }
        lg[tid] = a;
        g_sumq[q * 64 + tid] = s;
    }
    __syncthreads();

    if (tid < NM) {
        float mx = -1e30f;
        for (int m = 0; m < NM; m++) mx = fmaxf(mx, lg[m]);
        float den = 0.f;
        for (int m = 0; m < NM; m++) den += expf(lg[m] - mx);
        g_attn[q * 64 + tid] = expf(lg[tid] - mx) / den;
    } else {
        g_attn[q * 64 + tid] = 0.f;   // pad m in [50,64): weight 0 => inert
    }

    if (tid == 0) {
        float x = alpha_b[0];
        #pragma unroll
        for (int k = 0; k < 64; k++) x = fmaf(qe[k], alpha_w[k], x);
        g_alpha[q] = fmaxf(x, 0.f) + log1pf(expf(-fabsf(x)));
    }
    if (tid >= 1 && tid < 5) {
        int t = tid - 1;
        float x = beta_b[t];
        #pragma unroll
        for (int k = 0; k < 64; k++) x = fmaf(qe[k], beta_w[k * 4 + t], x);
        g_beta[q * 4 + t] = x;
    }
}

// ================= Phase A2: per-(question,response) erase/add =================
__global__ __launch_bounds__(128)
void build_qr_tables(const float* __restrict__ item_w,
                     const float* __restrict__ vp_w,
                     const float* __restrict__ vp_b,
                     const float* __restrict__ er_w,
                     const float* __restrict__ er_b,
                     const float* __restrict__ ad_w,
                     const float* __restrict__ ad_b) {
    int q = blockIdx.x;
    int v = threadIdx.x;             // 128 threads
    __shared__ float iv[64];
    __shared__ float veS[NK][NDV];

    if (v < 64) iv[v] = item_w[q * 64 + v];
    __syncthreads();

    float common = vp_b[v];
    #pragma unroll
    for (int i = 0; i < 64; i++) common = fmaf(iv[i], vp_w[i * NDV + v], common);
    #pragma unroll
    for (int r = 0; r < NK; r++) {
        float x = common;
        #pragma unroll
        for (int k = 0; k < NK; k++) {
            float rf = fmaxf(0.f, 1.f - fabsf((float)k - (float)r) * 0.25f);
            x = fmaf(rf, vp_w[(64 + k) * NDV + v], x);
        }
        veS[r][v] = x;
    }
    __syncthreads();

    int j = v;
    float eacc[NK], aacc[NK];
    #pragma unroll
    for (int r = 0; r < NK; r++) { eacc[r] = er_b[j]; aacc[r] = ad_b[j]; }
    for (int v2 = 0; v2 < NDV; v2++) {
        float we = er_w[v2 * NDV + j];
        float wa = ad_w[v2 * NDV + j];
        #pragma unroll
        for (int r = 0; r < NK; r++) {
            float t = veS[r][v2];
            eacc[r] = fmaf(t, we, eacc[r]);
            aacc[r] = fmaf(t, wa, aacc[r]);
        }
    }
    #pragma unroll
    for (int r = 0; r < NK; r++) {
        long base = ((long)q * NK + r) * NDV + j;
        g_ea[base] = make_float2(1.f / (1.f + expf(-eacc[r])), tanhf(aacc[r]));
    }
}

// ========================= Phase B: sequential scan =========================
// One CTA of 512 threads per batch element. NO per-step barriers: each warp is
// autonomous (owns 8 d-columns x 4 m-parts). m padded 50->64 = 32 packed pairs;
// part p owns pairs [8p,8p+8) = 16 attn floats loaded as 4 aligned LDG.128 from
// the L2-resident table (pad weights are 0 => inert). All loads prefetched one
// step ahead; read reduced with 2x in-quad shfl_xor.
__global__ __launch_bounds__(512, 1)
void scan_kernel(const int* __restrict__ questions,
                 const int* __restrict__ responses,
                 const float* __restrict__ init_mem) {
    int b = blockIdx.x;
    int tid = threadIdx.x;
    int part = tid & 3;
    int d = tid >> 2;                // 0..127
    __shared__ int qsh[NS + 1];      // q | (r<<16); [NS] = dup of last

    for (int i = tid; i < NS; i += 512)
        qsh[i] = questions[b * NS + i] | (responses[b * NS + i] << 16);
    if (tid == 0)
        qsh[NS] = questions[b * NS + NS - 1] | (responses[b * NS + NS - 1] << 16);

    // init mem: pair pi = 8*part + jj covers m = 2pi, 2pi+1 (zero for m >= 50)
    ull mem2[8];
    #pragma unroll
    for (int jj = 0; jj < 8; jj++) {
        int pi = 8 * part + jj;
        mem2[jj] = (pi < 25)
            ? pack2(init_mem[(2 * pi) * NDV + d], init_mem[(2 * pi + 1) * NDV + d])
            : 0ULL;
    }
    __syncthreads();                 // qsh ready; last sync in the kernel

    int v0 = qsh[0];
    int qc = v0 & 0xffff, rc = v0 >> 16;
    float2 ea_cur = g_ea[(qc * NK + rc) * NDV + d];
    ulonglong2 at_cur[4];
    {
        const ulonglong2* ap = (const ulonglong2*)(g_attn + qc * 64 + part * 16);
        at_cur[0] = ap[0]; at_cur[1] = ap[1]; at_cur[2] = ap[2]; at_cur[3] = ap[3];
    }

    float* outp = g_reads + ((long)b * NS) * NDV + d;

    for (int t = 0; t < NS; t++) {
        // prefetch step t+1 (L2-resident tables)
        int vn = qsh[t + 1];
        int qn = vn & 0xffff, rn = vn >> 16;
        float2 ea_nxt = g_ea[(qn * NK + rn) * NDV + d];
        ulonglong2 at_nxt[4];
        {
            const ulonglong2* ap = (const ulonglong2*)(g_attn + qn * 64 + part * 16);
            at_nxt[0] = ap[0]; at_nxt[1] = ap[1]; at_nxt[2] = ap[2]; at_nxt[3] = ap[3];
        }

        ull ne2 = pack2(-ea_cur.x, -ea_cur.x);
        ull a2  = pack2(ea_cur.y, ea_cur.y);

        ull r0 = 0ULL, r1 = 0ULL;
        #pragma unroll
        for (int u = 0; u < 4; u++) {
            ull w0 = at_cur[u].x, w1 = at_cur[u].y;
            ull m0 = mem2[2 * u], m1 = mem2[2 * u + 1];
            r0 = ffma2(w0, m0, r0);
            r1 = ffma2(w1, m1, r1);
            mem2[2 * u]     = ffma2(w0, ffma2(m0, ne2, a2), m0);
            mem2[2 * u + 1] = ffma2(w1, ffma2(m1, ne2, a2), m1);
        }
        float2 rr = unpack2(fadd2(r0, r1));
        float rsum = rr.x + rr.y;
        rsum += __shfl_xor_sync(0xffffffffu, rsum, 1);
        rsum += __shfl_xor_sync(0xffffffffu, rsum, 2);
        if (part == 0) outp[(long)t * NDV] = rsum;

        ea_cur = ea_nxt;
        at_cur[0] = at_nxt[0]; at_cur[1] = at_nxt[1];
        at_cur[2] = at_nxt[2]; at_cur[3] = at_nxt[3];
    }
}

// ===================== Phase C: summary / outputs =====================
// CT=32 positions/block, 128 threads; 8 pos-groups x 13 j-groups = 104 active.
// Positions interleaved (pos = pg + pp*8) for conflict-free LDS.128 on rS.
#define CT 32
__global__ __launch_bounds__(128)
void output_kernel(const int* __restrict__ questions,
                   const float* __restrict__ sum_w,    // (192,50); rows 0..127 used
                   const float* __restrict__ sum_b,
                   const float* __restrict__ theta_w,
                   const float* __restrict__ theta_b,
                   float* __restrict__ out) {
    __shared__ float rS[CT][132];    // reads tile; later reused as summary (CT x 52)
    __shared__ float wS[128 * 52];
    __shared__ float twS[52];

    int tid = threadIdx.x;
    long p0 = (long)blockIdx.x * CT;

    for (int i = tid; i < 128 * 52; i += 128) {
        int dd = i / 52, j = i % 52;
        wS[i] = (j < NDS) ? sum_w[dd * NDS + j] : 0.f;
    }
    if (tid < 52) twS[tid] = (tid < NDS) ? theta_w[tid] : 0.f;
    for (int i = tid; i < CT * 128; i += 128) {
        int pos = i >> 7, dd = i & 127;
        rS[pos][dd] = g_reads[p0 * 128 + i];
    }
    __syncthreads();

    int pg = tid / 13;
    int jg = tid - pg * 13;
    bool active = (tid < 104);
    int jbase = jg * 4;
    ull acc[4][2];
    if (active) {
        #pragma unroll
        for (int pp = 0; pp < 4; pp++) { acc[pp][0] = 0ULL; acc[pp][1] = 0ULL; }
        for (int dd0 = 0; dd0 < 128; dd0 += 4) {
            ulonglong2 wv[4];
            #pragma unroll
            for (int u = 0; u < 4; u++)
                wv[u] = *(const ulonglong2*)&wS[(dd0 + u) * 52 + jbase];
            #pragma unroll
            for (int pp = 0; pp < 4; pp++) {
                float4 rv = *(const float4*)&rS[pg + pp * 8][dd0];
                ull r0 = pack2(rv.x, rv.x);
                acc[pp][0] = ffma2(r0, wv[0].x, acc[pp][0]);
                acc[pp][1] = ffma2(r0, wv[0].y, acc[pp][1]);
                ull r1 = pack2(rv.y, rv.y);
                acc[pp][0] = ffma2(r1, wv[1].x, acc[pp][0]);
                acc[pp][1] = ffma2(r1, wv[1].y, acc[pp][1]);
                ull r2 = pack2(rv.z, rv.z);
                acc[pp][0] = ffma2(r2, wv[2].x, acc[pp][0]);
                acc[pp][1] = ffma2(r2, wv[2].y, acc[pp][1]);
                ull r3 = pack2(rv.w, rv.w);
                acc[pp][0] = ffma2(r3, wv[3].x, acc[pp][0]);
                acc[pp][1] = ffma2(r3, wv[3].y, acc[pp][1]);
            }
        }
    }
    __syncthreads();   // all reads of rS done; now reuse as summary tile

    float* sS = (float*)rS;          // CT x 52 summary
    if (active) {
        #pragma unroll
        for (int pp = 0; pp < 4; pp++) {
            int pos = pg + pp * 8;
            long p = p0 + pos;
            int q = questions[p];
            float2 a01 = unpack2(acc[pp][0]);
            float2 a23 = unpack2(acc[pp][1]);
            float av[4] = {a01.x, a01.y, a23.x, a23.y};
            #pragma unroll
            for (int jj = 0; jj < 4; jj++) {
                int j = jbase + jj;
                float s = 0.f;
                if (j < NDS)
                    s = tanhf(av[jj] + g_sumq[q * 64 + j] + sum_b[j]);
                sS[pos * 52 + j] = s;
            }
        }
    }
    __syncthreads();

    if (tid < CT) {
        long p = p0 + tid;
        int q = questions[p];
        float th = theta_b[0];
        #pragma unroll
        for (int j = 0; j < NDS; j++) th = fmaf(sS[tid * 52 + j], twS[j], th);
        th = tanhf(th);
        float al = g_alpha[q];
        float inter = th * al;
        float bt[4];
        #pragma unroll
        for (int t = 0; t < 4; t++) bt[t] = g_beta[q * 4 + t];
        float lg[5];
        lg[0] = 0.f;
        float c = 0.f;
        #pragma unroll
        for (int t = 0; t < 4; t++) { c += inter - bt[t]; lg[t + 1] = c; }
        float mx = lg[0];
        #pragma unroll
        for (int i = 1; i < 5; i++) mx = fmaxf(mx, lg[i]);
        float ex[5], den = 0.f;
        #pragma unroll
        for (int i = 0; i < 5; i++) { ex[i] = expf(lg[i] - mx); den += ex[i]; }
        float inv = 1.f / den;

        const long NBS = (long)NPOS;
        out[p]               = th;           // theta
        out[NBS + p]         = al;           // alpha
        #pragma unroll
        for (int t = 0; t < 4; t++) out[2 * NBS + p * 4 + t] = bt[t];   // beta
        #pragma unroll
        for (int i = 0; i < 5; i++) out[6 * NBS + p * 5 + i] = lg[i];   // logits
        #pragma unroll
        for (int i = 0; i < 5; i++) out[11 * NBS + p * 5 + i] = ex[i] * inv; // probs
    }
}

// ============================== launcher ==============================
extern "C" void kernel_launch(void* const* d_in, const int* in_sizes, int n_in,
                              void* d_out, int out_size) {
    const int*   questions    = (const int*)  d_in[0];
    const int*   responses    = (const int*)  d_in[1];
    const float* q_embed_w    = (const float*)d_in[2];
    const float* item_embed_w = (const float*)d_in[3];
    const float* value_proj_w = (const float*)d_in[4];
    const float* value_proj_b = (const float*)d_in[5];
    const float* key_mem      = (const float*)d_in[6];
    const float* init_mem     = (const float*)d_in[7];
    const float* erase_w      = (const float*)d_in[8];
    const float* erase_b      = (const float*)d_in[9];
    const float* add_w        = (const float*)d_in[10];
    const float* add_b        = (const float*)d_in[11];
    const float* summary_w    = (const float*)d_in[12];
    const float* summary_b    = (const float*)d_in[13];
    const float* theta_w      = (const float*)d_in[14];
    const float* theta_b      = (const float*)d_in[15];
    const float* alpha_w      = (const float*)d_in[16];
    const float* alpha_b      = (const float*)d_in[17];
    const float* beta_w       = (const float*)d_in[18];
    const float* beta_b       = (const float*)d_in[19];
    float* out = (float*)d_out;

    build_q_tables<<<NQ, 64>>>(q_embed_w, key_mem, summary_w,
                               alpha_w, alpha_b, beta_w, beta_b);
    build_qr_tables<<<NQ, 128>>>(item_embed_w, value_proj_w, value_proj_b,
                                 erase_w, erase_b, add_w, add_b);
    scan_kernel<<<NB, 512>>>(questions, responses, init_mem);
    output_kernel<<<NPOS / CT, 128>>>(questions, summary_w, summary_b,
                                      theta_w, theta_b, out);
}

// round 8
// speedup vs baseline: 2.1222x; 2.1222x over previous
#include <cuda_runtime.h>
#include <cuda_bf16.h>
#include <math.h>

// Problem constants
#define NB   128
#define NS   2048
#define NM   50
#define NDK  64
#define NDV  128
#define NK   5
#define NDS  50
#define NQ   1001
#define NPOS (NB*NS)   // 262144

typedef unsigned long long ull;

// ---- packed f32x2 helpers (bit-identical per lane to scalar fp32) ----
__device__ __forceinline__ ull ffma2(ull a, ull b, ull c) {
    ull d;
    asm("fma.rn.f32x2 %0, %1, %2, %3;" : "=l"(d) : "l"(a), "l"(b), "l"(c));
    return d;
}
__device__ __forceinline__ ull fadd2(ull a, ull b) {
    ull d;
    asm("add.rn.f32x2 %0, %1, %2;" : "=l"(d) : "l"(a), "l"(b));
    return d;
}
__device__ __forceinline__ ull pack2(float lo, float hi) {
    ull r; asm("mov.b64 %0, {%1,%2};" : "=l"(r) : "f"(lo), "f"(hi)); return r;
}
__device__ __forceinline__ float2 unpack2(ull v) {
    float2 f; asm("mov.b64 {%0,%1}, %2;" : "=f"(f.x), "=f"(f.y) : "l"(v)); return f;
}

// ---- cp.async helpers ----
__device__ __forceinline__ void cp_async8(void* dst, const void* src) {
    unsigned s = (unsigned)__cvta_generic_to_shared(dst);
    asm volatile("cp.async.ca.shared.global [%0], [%1], 8;" :: "r"(s), "l"(src));
}
__device__ __forceinline__ void cp_async16(void* dst, const void* src) {
    unsigned s = (unsigned)__cvta_generic_to_shared(dst);
    asm volatile("cp.async.ca.shared.global [%0], [%1], 16;" :: "r"(s), "l"(src));
}
__device__ __forceinline__ void cp_commit() {
    asm volatile("cp.async.commit_group;");
}
__device__ __forceinline__ void cp_wait3() {
    asm volatile("cp.async.wait_group 3;");
}

// -------- scratch (__device__ globals; no runtime allocation) --------
__device__ float  g_attn [NQ * 64];            // softmax(q_e @ key_mem^T); [50,64) ZERO
__device__ float  g_sumq [NQ * 64];            // q_e @ summary_w[128:192], stride 64
__device__ float  g_alpha[NQ];
__device__ float  g_beta [NQ * 4];
__device__ float2 g_ea   [NQ * NK * NDV];      // (.x=erase sigmoid, .y=add tanh)
__device__ float  g_reads[(long)NB * NS * NDV];// 134 MB

// ======================= Phase A1: per-question tables =======================
__global__ void build_q_tables(const float* __restrict__ qe_w,
                               const float* __restrict__ key_mem,
                               const float* __restrict__ sum_w,
                               const float* __restrict__ alpha_w,
                               const float* __restrict__ alpha_b,
                               const float* __restrict__ beta_w,
                               const float* __restrict__ beta_b) {
    int q = blockIdx.x;
    int tid = threadIdx.x;           // 64 threads
    __shared__ float qe[64];
    __shared__ float lg[NM];
    qe[tid] = qe_w[q * 64 + tid];
    __syncthreads();

    if (tid < NM) {
        float a = 0.f, s = 0.f;
        #pragma unroll
        for (int k = 0; k < 64; k++) {
            float qk = qe[k];
            a = fmaf(qk, key_mem[tid * 64 + k], a);
            s = fmaf(qk, sum_w[(128 + k) * NDS + tid], s);
        }
        lg[tid] = a;
        g_sumq[q * 64 + tid] = s;
    }
    __syncthreads();

    if (tid < NM) {
        float mx = -1e30f;
        for (int m = 0; m < NM; m++) mx = fmaxf(mx, lg[m]);
        float den = 0.f;
        for (int m = 0; m < NM; m++) den += expf(lg[m] - mx);
        g_attn[q * 64 + tid] = expf(lg[tid] - mx) / den;
    } else {
        g_attn[q * 64 + tid] = 0.f;   // pad m in [50,64): weight 0 => inert
    }

    if (tid == 0) {
        float x = alpha_b[0];
        #pragma unroll
        for (int k = 0; k < 64; k++) x = fmaf(qe[k], alpha_w[k], x);
        g_alpha[q] = fmaxf(x, 0.f) + log1pf(expf(-fabsf(x)));
    }
    if (tid >= 1 && tid < 5) {
        int t = tid - 1;
        float x = beta_b[t];
        #pragma unroll
        for (int k = 0; k < 64; k++) x = fmaf(qe[k], beta_w[k * 4 + t], x);
        g_beta[q * 4 + t] = x;
    }
}

// ================= Phase A2: per-(question,response) erase/add =================
__global__ __launch_bounds__(128)
void build_qr_tables(const float* __restrict__ item_w,
                     const float* __restrict__ vp_w,
                     const float* __restrict__ vp_b,
                     const float* __restrict__ er_w,
                     const float* __restrict__ er_b,
                     const float* __restrict__ ad_w,
                     const float* __restrict__ ad_b) {
    int q = blockIdx.x;
    int v = threadIdx.x;             // 128 threads
    __shared__ float iv[64];
    __shared__ float veS[NK][NDV];

    if (v < 64) iv[v] = item_w[q * 64 + v];
    __syncthreads();

    float common = vp_b[v];
    #pragma unroll
    for (int i = 0; i < 64; i++) common = fmaf(iv[i], vp_w[i * NDV + v], common);
    #pragma unroll
    for (int r = 0; r < NK; r++) {
        float x = common;
        #pragma unroll
        for (int k = 0; k < NK; k++) {
            float rf = fmaxf(0.f, 1.f - fabsf((float)k - (float)r) * 0.25f);
            x = fmaf(rf, vp_w[(64 + k) * NDV + v], x);
        }
        veS[r][v] = x;
    }
    __syncthreads();

    int j = v;
    float eacc[NK], aacc[NK];
    #pragma unroll
    for (int r = 0; r < NK; r++) { eacc[r] = er_b[j]; aacc[r] = ad_b[j]; }
    for (int v2 = 0; v2 < NDV; v2++) {
        float we = er_w[v2 * NDV + j];
        float wa = ad_w[v2 * NDV + j];
        #pragma unroll
        for (int r = 0; r < NK; r++) {
            float t = veS[r][v2];
            eacc[r] = fmaf(t, we, eacc[r]);
            aacc[r] = fmaf(t, wa, aacc[r]);
        }
    }
    #pragma unroll
    for (int r = 0; r < NK; r++) {
        long base = ((long)q * NK + r) * NDV + j;
        g_ea[base] = make_float2(1.f / (1.f + expf(-eacc[r])), tanhf(aacc[r]));
    }
}

// ========================= Phase B: sequential scan =========================
// One CTA of 256 threads per batch element. 2-way m split (part = tid&1,
// 13 packed pairs each; m padded 50->52, pad weights 0). Tables are staged
// into a shared-memory ring by cp.async, 8 steps (4 groups of 2) ahead:
// the compute loop never has an LDG on its critical path. One barrier per
// 2 steps; read reduced by a single in-pair shfl_xor.
#define RD 6          // ring slots (each slot = 2 steps); > prefetch depth 4
__global__ __launch_bounds__(256, 1)
void scan_kernel(const int* __restrict__ questions,
                 const int* __restrict__ responses,
                 const float* __restrict__ init_mem) {
    int b = blockIdx.x;
    int tid = threadIdx.x;
    int part = tid & 1;
    int d = tid >> 1;                // 0..127
    __shared__ int    qsh[NS + 16];  // q | (r<<16), padded with dup of last
    __shared__ float2 ea_ring[RD][2][NDV];
    __shared__ float  attn_ring[RD][2][56];

    for (int i = tid; i < NS; i += 256)
        qsh[i] = questions[b * NS + i] | (responses[b * NS + i] << 16);
    if (tid < 16)
        qsh[NS + tid] = questions[b * NS + NS - 1] | (responses[b * NS + NS - 1] << 16);

    // init mem: part p owns pairs [13p, 13p+13); pair pi covers m = 2pi, 2pi+1
    ull mem2[13];
    #pragma unroll
    for (int jj = 0; jj < 13; jj++) {
        int pi = 13 * part + jj;
        float lo = (2 * pi < NM)     ? init_mem[(2 * pi) * NDV + d]     : 0.f;
        float hi = (2 * pi + 1 < NM) ? init_mem[(2 * pi + 1) * NDV + d] : 0.f;
        mem2[jj] = pack2(lo, hi);
    }
    __syncthreads();                 // qsh ready

    // prologue: issue groups for step-pairs 0..3 (steps 0..7)
    #pragma unroll
    for (int p = 0; p < 4; p++) {
        int slot = p;                // p < RD
        #pragma unroll
        for (int k = 0; k < 2; k++) {
            int v = qsh[2 * p + k];
            int qq = v & 0xffff, rr = v >> 16;
            if (tid < 128) {
                cp_async8(&ea_ring[slot][k][tid], &g_ea[(qq * NK + rr) * NDV + tid]);
            } else if (tid < 141) {
                int i = tid - 128;   // 0..12 -> 13x16B = 52 floats
                cp_async16(&attn_ring[slot][k][i * 4], g_attn + qq * 64 + i * 4);
            }
        }
        cp_commit();
    }

    float* outp = g_reads + ((long)b * NS) * NDV + d;

    for (int p = 0; p < NS / 2; p++) {
        cp_wait3();                  // group p complete
        __syncthreads();             // ring slot p%RD visible to all
        int slot = p % RD;

        #pragma unroll
        for (int k = 0; k < 2; k++) {
            int t = 2 * p + k;
            float2 ea = ea_ring[slot][k][d];
            ull ne2 = pack2(-ea.x, -ea.x);
            ull a2  = pack2(ea.y, ea.y);
            const float2* at = (const float2*)attn_ring[slot][k] + 13 * part;

            ull r0 = 0ULL, r1 = 0ULL;
            #pragma unroll
            for (int jj = 0; jj < 13; jj++) {
                float2 wf = at[jj];
                ull w2 = pack2(wf.x, wf.y);
                ull mo = mem2[jj];
                if (jj & 1) r1 = ffma2(w2, mo, r1);
                else        r0 = ffma2(w2, mo, r0);
                mem2[jj] = ffma2(w2, ffma2(mo, ne2, a2), mo);
            }
            float2 rr = unpack2(fadd2(r0, r1));
            float rsum = rr.x + rr.y;
            rsum += __shfl_xor_sync(0xffffffffu, rsum, 1);
            if (part == 0) outp[(long)t * NDV] = rsum;
        }

        // issue group p+4 into slot (p+4)%RD (never a slot still being read)
        int pn = p + 4;
        if (pn < NS / 2 + 4) {       // clamp via padded qsh; harmless re-issue at tail
            int slotn = pn % RD;
            #pragma unroll
            for (int k = 0; k < 2; k++) {
                int idx = 2 * pn + k;
                if (idx > NS + 14) idx = NS + 14;
                int v = qsh[idx];
                int qq = v & 0xffff, rr2 = v >> 16;
                if (tid < 128) {
                    cp_async8(&ea_ring[slotn][k][tid], &g_ea[(qq * NK + rr2) * NDV + tid]);
                } else if (tid < 141) {
                    int i = tid - 128;
                    cp_async16(&attn_ring[slotn][k][i * 4], g_attn + qq * 64 + i * 4);
                }
            }
        }
        cp_commit();                 // always commit to keep group count in sync
    }
}

// ===================== Phase C: summary / outputs =====================
// CT=32 positions/block, 128 threads; 8 pos-groups x 13 j-groups = 104 active.
// Positions interleaved (pos = pg + pp*8) for conflict-free LDS.128 on rS.
#define CT 32
__global__ __launch_bounds__(128)
void output_kernel(const int* __restrict__ questions,
                   const float* __restrict__ sum_w,    // (192,50); rows 0..127 used
                   const float* __restrict__ sum_b,
                   const float* __restrict__ theta_w,
                   const float* __restrict__ theta_b,
                   float* __restrict__ out) {
    __shared__ float rS[CT][132];    // reads tile; later reused as summary (CT x 52)
    __shared__ float wS[128 * 52];
    __shared__ float twS[52];

    int tid = threadIdx.x;
    long p0 = (long)blockIdx.x * CT;

    for (int i = tid; i < 128 * 52; i += 128) {
        int dd = i / 52, j = i % 52;
        wS[i] = (j < NDS) ? sum_w[dd * NDS + j] : 0.f;
    }
    if (tid < 52) twS[tid] = (tid < NDS) ? theta_w[tid] : 0.f;
    for (int i = tid; i < CT * 128; i += 128) {
        int pos = i >> 7, dd = i & 127;
        rS[pos][dd] = g_reads[p0 * 128 + i];
    }
    __syncthreads();

    int pg = tid / 13;
    int jg = tid - pg * 13;
    bool active = (tid < 104);
    int jbase = jg * 4;
    ull acc[4][2];
    if (active) {
        #pragma unroll
        for (int pp = 0; pp < 4; pp++) { acc[pp][0] = 0ULL; acc[pp][1] = 0ULL; }
        for (int dd0 = 0; dd0 < 128; dd0 += 4) {
            ulonglong2 wv[4];
            #pragma unroll
            for (int u = 0; u < 4; u++)
                wv[u] = *(const ulonglong2*)&wS[(dd0 + u) * 52 + jbase];
            #pragma unroll
            for (int pp = 0; pp < 4; pp++) {
                float4 rv = *(const float4*)&rS[pg + pp * 8][dd0];
                ull r0 = pack2(rv.x, rv.x);
                acc[pp][0] = ffma2(r0, wv[0].x, acc[pp][0]);
                acc[pp][1] = ffma2(r0, wv[0].y, acc[pp][1]);
                ull r1 = pack2(rv.y, rv.y);
                acc[pp][0] = ffma2(r1, wv[1].x, acc[pp][0]);
                acc[pp][1] = ffma2(r1, wv[1].y, acc[pp][1]);
                ull r2 = pack2(rv.z, rv.z);
                acc[pp][0] = ffma2(r2, wv[2].x, acc[pp][0]);
                acc[pp][1] = ffma2(r2, wv[2].y, acc[pp][1]);
                ull r3 = pack2(rv.w, rv.w);
                acc[pp][0] = ffma2(r3, wv[3].x, acc[pp][0]);
                acc[pp][1] = ffma2(r3, wv[3].y, acc[pp][1]);
            }
        }
    }
    __syncthreads();   // all reads of rS done; now reuse as summary tile

    float* sS = (float*)rS;          // CT x 52 summary
    if (active) {
        #pragma unroll
        for (int pp = 0; pp < 4; pp++) {
            int pos = pg + pp * 8;
            long p = p0 + pos;
            int q = questions[p];
            float2 a01 = unpack2(acc[pp][0]);
            float2 a23 = unpack2(acc[pp][1]);
            float av[4] = {a01.x, a01.y, a23.x, a23.y};
            #pragma unroll
            for (int jj = 0; jj < 4; jj++) {
                int j = jbase + jj;
                float s = 0.f;
                if (j < NDS)
                    s = tanhf(av[jj] + g_sumq[q * 64 + j] + sum_b[j]);
                sS[pos * 52 + j] = s;
            }
        }
    }
    __syncthreads();

    if (tid < CT) {
        long p = p0 + tid;
        int q = questions[p];
        float th = theta_b[0];
        #pragma unroll
        for (int j = 0; j < NDS; j++) th = fmaf(sS[tid * 52 + j], twS[j], th);
        th = tanhf(th);
        float al = g_alpha[q];
        float inter = th * al;
        float bt[4];
        #pragma unroll
        for (int t = 0; t < 4; t++) bt[t] = g_beta[q * 4 + t];
        float lg[5];
        lg[0] = 0.f;
        float c = 0.f;
        #pragma unroll
        for (int t = 0; t < 4; t++) { c += inter - bt[t]; lg[t + 1] = c; }
        float mx = lg[0];
        #pragma unroll
        for (int i = 1; i < 5; i++) mx = fmaxf(mx, lg[i]);
        float ex[5], den = 0.f;
        #pragma unroll
        for (int i = 0; i < 5; i++) { ex[i] = expf(lg[i] - mx); den += ex[i]; }
        float inv = 1.f / den;

        const long NBS = (long)NPOS;
        out[p]               = th;           // theta
        out[NBS + p]         = al;           // alpha
        #pragma unroll
        for (int t = 0; t < 4; t++) out[2 * NBS + p * 4 + t] = bt[t];   // beta
        #pragma unroll
        for (int i = 0; i < 5; i++) out[6 * NBS + p * 5 + i] = lg[i];   // logits
        #pragma unroll
        for (int i = 0; i < 5; i++) out[11 * NBS + p * 5 + i] = ex[i] * inv; // probs
    }
}

// ============================== launcher ==============================
extern "C" void kernel_launch(void* const* d_in, const int* in_sizes, int n_in,
                              void* d_out, int out_size) {
    const int*   questions    = (const int*)  d_in[0];
    const int*   responses    = (const int*)  d_in[1];
    const float* q_embed_w    = (const float*)d_in[2];
    const float* item_embed_w = (const float*)d_in[3];
    const float* value_proj_w = (const float*)d_in[4];
    const float* value_proj_b = (const float*)d_in[5];
    const float* key_mem      = (const float*)d_in[6];
    const float* init_mem     = (const float*)d_in[7];
    const float* erase_w      = (const float*)d_in[8];
    const float* erase_b      = (const float*)d_in[9];
    const float* add_w        = (const float*)d_in[10];
    const float* add_b        = (const float*)d_in[11];
    const float* summary_w    = (const float*)d_in[12];
    const float* summary_b    = (const float*)d_in[13];
    const float* theta_w      = (const float*)d_in[14];
    const float* theta_b      = (const float*)d_in[15];
    const float* alpha_w      = (const float*)d_in[16];
    const float* alpha_b      = (const float*)d_in[17];
    const float* beta_w       = (const float*)d_in[18];
    const float* beta_b       = (const float*)d_in[19];
    float* out = (float*)d_out;

    build_q_tables<<<NQ, 64>>>(q_embed_w, key_mem, summary_w,
                               alpha_w, alpha_b, beta_w, beta_b);
    build_qr_tables<<<NQ, 128>>>(item_embed_w, value_proj_w, value_proj_b,
                                 erase_w, erase_b, add_w, add_b);
    scan_kernel<<<NB, 256>>>(questions, responses, init_mem);
    output_kernel<<<NPOS / CT, 128>>>(questions, summary_w, summary_b,
                                      theta_w, theta_b, out);
}

// round 9
// speedup vs baseline: 2.4490x; 1.1540x over previous
#include <cuda_runtime.h>
#include <cuda_bf16.h>
#include <math.h>

// Problem constants
#define NB   128
#define NS   2048
#define NM   50
#define NDK  64
#define NDV  128
#define NK   5
#define NDS  50
#define NQ   1001
#define NPOS (NB*NS)   // 262144

typedef unsigned long long ull;

// ---- packed f32x2 helpers (bit-identical per lane to scalar fp32) ----
__device__ __forceinline__ ull ffma2(ull a, ull b, ull c) {
    ull d;
    asm("fma.rn.f32x2 %0, %1, %2, %3;" : "=l"(d) : "l"(a), "l"(b), "l"(c));
    return d;
}
__device__ __forceinline__ ull fadd2(ull a, ull b) {
    ull d;
    asm("add.rn.f32x2 %0, %1, %2;" : "=l"(d) : "l"(a), "l"(b));
    return d;
}
__device__ __forceinline__ ull pack2(float lo, float hi) {
    ull r; asm("mov.b64 %0, {%1,%2};" : "=l"(r) : "f"(lo), "f"(hi)); return r;
}
__device__ __forceinline__ float2 unpack2(ull v) {
    float2 f; asm("mov.b64 {%0,%1}, %2;" : "=f"(f.x), "=f"(f.y) : "l"(v)); return f;
}

// ---- cp.async helpers ----
__device__ __forceinline__ void cp_async8(void* dst, const void* src) {
    unsigned s = (unsigned)__cvta_generic_to_shared(dst);
    asm volatile("cp.async.ca.shared.global [%0], [%1], 8;" :: "r"(s), "l"(src));
}
__device__ __forceinline__ void cp_async16(void* dst, const void* src) {
    unsigned s = (unsigned)__cvta_generic_to_shared(dst);
    asm volatile("cp.async.ca.shared.global [%0], [%1], 16;" :: "r"(s), "l"(src));
}
__device__ __forceinline__ void cp_commit() {
    asm volatile("cp.async.commit_group;");
}
__device__ __forceinline__ void cp_wait3() {
    asm volatile("cp.async.wait_group 3;");
}

// -------- scratch (__device__ globals; no runtime allocation) --------
__device__ float  g_attn [NQ * 64];            // softmax(q_e @ key_mem^T); [50,64) ZERO
__device__ float  g_sumq [NQ * 64];            // q_e @ summary_w[128:192], stride 64
__device__ float  g_alpha[NQ];
__device__ float  g_beta [NQ * 4];
__device__ float2 g_ea   [NQ * NK * NDV];      // (.x=erase sigmoid, .y=add tanh)
__device__ float  g_reads[(long)NB * NS * NDV];// 134 MB

// ======================= Phase A1: per-question tables =======================
__global__ void build_q_tables(const float* __restrict__ qe_w,
                               const float* __restrict__ key_mem,
                               const float* __restrict__ sum_w,
                               const float* __restrict__ alpha_w,
                               const float* __restrict__ alpha_b,
                               const float* __restrict__ beta_w,
                               const float* __restrict__ beta_b) {
    int q = blockIdx.x;
    int tid = threadIdx.x;           // 64 threads
    __shared__ float qe[64];
    __shared__ float lg[NM];
    qe[tid] = qe_w[q * 64 + tid];
    __syncthreads();

    if (tid < NM) {
        float a = 0.f, s = 0.f;
        #pragma unroll
        for (int k = 0; k < 64; k++) {
            float qk = qe[k];
            a = fmaf(qk, key_mem[tid * 64 + k], a);
            s = fmaf(qk, sum_w[(128 + k) * NDS + tid], s);
        }
        lg[tid] = a;
        g_sumq[q * 64 + tid] = s;
    }
    __syncthreads();

    if (tid < NM) {
        float mx = -1e30f;
        for (int m = 0; m < NM; m++) mx = fmaxf(mx, lg[m]);
        float den = 0.f;
        for (int m = 0; m < NM; m++) den += expf(lg[m] - mx);
        g_attn[q * 64 + tid] = expf(lg[tid] - mx) / den;
    } else {
        g_attn[q * 64 + tid] = 0.f;   // pad m in [50,64): weight 0 => inert
    }

    if (tid == 0) {
        float x = alpha_b[0];
        #pragma unroll
        for (int k = 0; k < 64; k++) x = fmaf(qe[k], alpha_w[k], x);
        g_alpha[q] = fmaxf(x, 0.f) + log1pf(expf(-fabsf(x)));
    }
    if (tid >= 1 && tid < 5) {
        int t = tid - 1;
        float x = beta_b[t];
        #pragma unroll
        for (int k = 0; k < 64; k++) x = fmaf(qe[k], beta_w[k * 4 + t], x);
        g_beta[q * 4 + t] = x;
    }
}

// ================= Phase A2: per-(question,response) erase/add =================
__global__ __launch_bounds__(128)
void build_qr_tables(const float* __restrict__ item_w,
                     const float* __restrict__ vp_w,
                     const float* __restrict__ vp_b,
                     const float* __restrict__ er_w,
                     const float* __restrict__ er_b,
                     const float* __restrict__ ad_w,
                     const float* __restrict__ ad_b) {
    int q = blockIdx.x;
    int v = threadIdx.x;             // 128 threads
    __shared__ float iv[64];
    __shared__ float veS[NK][NDV];

    if (v < 64) iv[v] = item_w[q * 64 + v];
    __syncthreads();

    float common = vp_b[v];
    #pragma unroll
    for (int i = 0; i < 64; i++) common = fmaf(iv[i], vp_w[i * NDV + v], common);
    #pragma unroll
    for (int r = 0; r < NK; r++) {
        float x = common;
        #pragma unroll
        for (int k = 0; k < NK; k++) {
            float rf = fmaxf(0.f, 1.f - fabsf((float)k - (float)r) * 0.25f);
            x = fmaf(rf, vp_w[(64 + k) * NDV + v], x);
        }
        veS[r][v] = x;
    }
    __syncthreads();

    int j = v;
    float eacc[NK], aacc[NK];
    #pragma unroll
    for (int r = 0; r < NK; r++) { eacc[r] = er_b[j]; aacc[r] = ad_b[j]; }
    for (int v2 = 0; v2 < NDV; v2++) {
        float we = er_w[v2 * NDV + j];
        float wa = ad_w[v2 * NDV + j];
        #pragma unroll
        for (int r = 0; r < NK; r++) {
            float t = veS[r][v2];
            eacc[r] = fmaf(t, we, eacc[r]);
            aacc[r] = fmaf(t, wa, aacc[r]);
        }
    }
    #pragma unroll
    for (int r = 0; r < NK; r++) {
        long base = ((long)q * NK + r) * NDV + j;
        g_ea[base] = make_float2(1.f / (1.f + expf(-eacc[r])), tanhf(aacc[r]));
    }
}

// ========================= Phase B: sequential scan =========================
// One CTA of 256 threads per batch element. 2-way m split (part = tid&1,
// 13 packed pairs each; m padded 50->52, pad weights 0). Tables staged into a
// smem ring by cp.async in slots of 4 STEPS, 4 slots (16 steps) ahead: no LDG
// on the critical path and only ONE barrier + ONE wait per 4 steps.
#define SLOT 4        // steps per ring slot / cp.async group
#define RD   6        // ring slots; > prefetch depth 4
__global__ __launch_bounds__(256, 1)
void scan_kernel(const int* __restrict__ questions,
                 const int* __restrict__ responses,
                 const float* __restrict__ init_mem) {
    int b = blockIdx.x;
    int tid = threadIdx.x;
    int part = tid & 1;
    int d = tid >> 1;                // 0..127
    __shared__ int    qsh[NS + 16];  // q | (r<<16), padded with dup of last
    __shared__ float2 ea_ring[RD][SLOT][NDV];
    __shared__ float  attn_ring[RD][SLOT][56];

    for (int i = tid; i < NS; i += 256)
        qsh[i] = questions[b * NS + i] | (responses[b * NS + i] << 16);
    if (tid < 16)
        qsh[NS + tid] = questions[b * NS + NS - 1] | (responses[b * NS + NS - 1] << 16);

    // cp duty assignment (fixed per thread):
    //  ea:   every thread loads element d2 for steps kk*2 and kk*2+1 of the slot
    //  attn: threads 0..51 load one 16B chunk (step ka, chunk ia)
    int d2 = tid & 127;
    int kk = tid >> 7;               // 0 or 1
    int ka = (tid < 52) ? (tid / 13) : 0;
    int ia = (tid < 52) ? (tid % 13) : 0;

    // init mem: part p owns pairs [13p, 13p+13); pair pi covers m = 2pi, 2pi+1
    ull mem2[13];
    #pragma unroll
    for (int jj = 0; jj < 13; jj++) {
        int pi = 13 * part + jj;
        float lo = (2 * pi < NM)     ? init_mem[(2 * pi) * NDV + d]     : 0.f;
        float hi = (2 * pi + 1 < NM) ? init_mem[(2 * pi + 1) * NDV + d] : 0.f;
        mem2[jj] = pack2(lo, hi);
    }
    __syncthreads();                 // qsh ready

    // prologue: issue slots 0..3 (steps 0..15)
    #pragma unroll
    for (int p = 0; p < 4; p++) {
        #pragma unroll
        for (int kq = 0; kq < 2; kq++) {
            int k = kk * 2 + kq;
            int v = qsh[SLOT * p + k];
            int qq = v & 0xffff, rr = v >> 16;
            cp_async8(&ea_ring[p][k][d2], &g_ea[(qq * NK + rr) * NDV + d2]);
        }
        if (tid < 52) {
            int v = qsh[SLOT * p + ka];
            int qq = v & 0xffff;
            cp_async16(&attn_ring[p][ka][ia * 4], g_attn + qq * 64 + ia * 4);
        }
        cp_commit();
    }

    float* outp = g_reads + ((long)b * NS) * NDV + d;

    for (int p = 0; p < NS / SLOT; p++) {
        cp_wait3();                  // slot p complete
        __syncthreads();             // ring slot p%RD visible to all
        int slot = p % RD;

        #pragma unroll
        for (int k = 0; k < SLOT; k++) {
            int t = SLOT * p + k;
            float2 ea = ea_ring[slot][k][d];
            ull ne2 = pack2(-ea.x, -ea.x);
            ull a2  = pack2(ea.y, ea.y);
            const float2* at = (const float2*)attn_ring[slot][k] + 13 * part;

            ull r0 = 0ULL, r1 = 0ULL;
            #pragma unroll
            for (int jj = 0; jj < 13; jj++) {
                float2 wf = at[jj];
                ull w2 = pack2(wf.x, wf.y);
                ull mo = mem2[jj];
                if (jj & 1) r1 = ffma2(w2, mo, r1);
                else        r0 = ffma2(w2, mo, r0);
                mem2[jj] = ffma2(w2, ffma2(mo, ne2, a2), mo);
            }
            float2 rr = unpack2(fadd2(r0, r1));
            float rsum = rr.x + rr.y;
            rsum += __shfl_xor_sync(0xffffffffu, rsum, 1);
            if (part == 0) outp[(long)t * NDV] = rsum;
        }

        // issue slot p+4 into ring slot (p+4)%RD (last read at iter p-2: safe)
        int pn = p + 4;
        {
            #pragma unroll
            for (int kq = 0; kq < 2; kq++) {
                int k = kk * 2 + kq;
                int idx = SLOT * pn + k;
                if (idx > NS + 15) idx = NS + 15;
                int v = qsh[idx];
                int qq = v & 0xffff, rr2 = v >> 16;
                cp_async8(&ea_ring[pn % RD][k][d2], &g_ea[(qq * NK + rr2) * NDV + d2]);
            }
            if (tid < 52) {
                int idx = SLOT * pn + ka;
                if (idx > NS + 15) idx = NS + 15;
                int v = qsh[idx];
                int qq = v & 0xffff;
                cp_async16(&attn_ring[pn % RD][ka][ia * 4], g_attn + qq * 64 + ia * 4);
            }
        }
        cp_commit();                 // keep group count in sync
    }
}

// ===================== Phase C: summary / outputs =====================
// CT=32 positions/block, 128 threads; 8 pos-groups x 13 j-groups = 104 active.
// Positions interleaved (pos = pg + pp*8) for conflict-free LDS.128 on rS.
#define CT 32
__global__ __launch_bounds__(128)
void output_kernel(const int* __restrict__ questions,
                   const float* __restrict__ sum_w,    // (192,50); rows 0..127 used
                   const float* __restrict__ sum_b,
                   const float* __restrict__ theta_w,
                   const float* __restrict__ theta_b,
                   float* __restrict__ out) {
    __shared__ float rS[CT][132];    // reads tile; later reused as summary (CT x 52)
    __shared__ float wS[128 * 52];
    __shared__ float twS[52];

    int tid = threadIdx.x;
    long p0 = (long)blockIdx.x * CT;

    for (int i = tid; i < 128 * 52; i += 128) {
        int dd = i / 52, j = i % 52;
        wS[i] = (j < NDS) ? sum_w[dd * NDS + j] : 0.f;
    }
    if (tid < 52) twS[tid] = (tid < NDS) ? theta_w[tid] : 0.f;
    for (int i = tid; i < CT * 128; i += 128) {
        int pos = i >> 7, dd = i & 127;
        rS[pos][dd] = g_reads[p0 * 128 + i];
    }
    __syncthreads();

    int pg = tid / 13;
    int jg = tid - pg * 13;
    bool active = (tid < 104);
    int jbase = jg * 4;
    ull acc[4][2];
    if (active) {
        #pragma unroll
        for (int pp = 0; pp < 4; pp++) { acc[pp][0] = 0ULL; acc[pp][1] = 0ULL; }
        for (int dd0 = 0; dd0 < 128; dd0 += 4) {
            ulonglong2 wv[4];
            #pragma unroll
            for (int u = 0; u < 4; u++)
                wv[u] = *(const ulonglong2*)&wS[(dd0 + u) * 52 + jbase];
            #pragma unroll
            for (int pp = 0; pp < 4; pp++) {
                float4 rv = *(const float4*)&rS[pg + pp * 8][dd0];
                ull r0 = pack2(rv.x, rv.x);
                acc[pp][0] = ffma2(r0, wv[0].x, acc[pp][0]);
                acc[pp][1] = ffma2(r0, wv[0].y, acc[pp][1]);
                ull r1 = pack2(rv.y, rv.y);
                acc[pp][0] = ffma2(r1, wv[1].x, acc[pp][0]);
                acc[pp][1] = ffma2(r1, wv[1].y, acc[pp][1]);
                ull r2 = pack2(rv.z, rv.z);
                acc[pp][0] = ffma2(r2, wv[2].x, acc[pp][0]);
                acc[pp][1] = ffma2(r2, wv[2].y, acc[pp][1]);
                ull r3 = pack2(rv.w, rv.w);
                acc[pp][0] = ffma2(r3, wv[3].x, acc[pp][0]);
                acc[pp][1] = ffma2(r3, wv[3].y, acc[pp][1]);
            }
        }
    }
    __syncthreads();   // all reads of rS done; now reuse as summary tile

    float* sS = (float*)rS;          // CT x 52 summary
    if (active) {
        #pragma unroll
        for (int pp = 0; pp < 4; pp++) {
            int pos = pg + pp * 8;
            long p = p0 + pos;
            int q = questions[p];
            float2 a01 = unpack2(acc[pp][0]);
            float2 a23 = unpack2(acc[pp][1]);
            float av[4] = {a01.x, a01.y, a23.x, a23.y};
            #pragma unroll
            for (int jj = 0; jj < 4; jj++) {
                int j = jbase + jj;
                float s = 0.f;
                if (j < NDS)
                    s = tanhf(av[jj] + g_sumq[q * 64 + j] + sum_b[j]);
                sS[pos * 52 + j] = s;
            }
        }
    }
    __syncthreads();

    if (tid < CT) {
        long p = p0 + tid;
        int q = questions[p];
        float th = theta_b[0];
        #pragma unroll
        for (int j = 0; j < NDS; j++) th = fmaf(sS[tid * 52 + j], twS[j], th);
        th = tanhf(th);
        float al = g_alpha[q];
        float inter = th * al;
        float bt[4];
        #pragma unroll
        for (int t = 0; t < 4; t++) bt[t] = g_beta[q * 4 + t];
        float lg[5];
        lg[0] = 0.f;
        float c = 0.f;
        #pragma unroll
        for (int t = 0; t < 4; t++) { c += inter - bt[t]; lg[t + 1] = c; }
        float mx = lg[0];
        #pragma unroll
        for (int i = 1; i < 5; i++) mx = fmaxf(mx, lg[i]);
        float ex[5], den = 0.f;
        #pragma unroll
        for (int i = 0; i < 5; i++) { ex[i] = expf(lg[i] - mx); den += ex[i]; }
        float inv = 1.f / den;

        const long NBS = (long)NPOS;
        out[p]               = th;           // theta
        out[NBS + p]         = al;           // alpha
        #pragma unroll
        for (int t = 0; t < 4; t++) out[2 * NBS + p * 4 + t] = bt[t];   // beta
        #pragma unroll
        for (int i = 0; i < 5; i++) out[6 * NBS + p * 5 + i] = lg[i];   // logits
        #pragma unroll
        for (int i = 0; i < 5; i++) out[11 * NBS + p * 5 + i] = ex[i] * inv; // probs
    }
}

// ============================== launcher ==============================
extern "C" void kernel_launch(void* const* d_in, const int* in_sizes, int n_in,
                              void* d_out, int out_size) {
    const int*   questions    = (const int*)  d_in[0];
    const int*   responses    = (const int*)  d_in[1];
    const float* q_embed_w    = (const float*)d_in[2];
    const float* item_embed_w = (const float*)d_in[3];
    const float* value_proj_w = (const float*)d_in[4];
    const float* value_proj_b = (const float*)d_in[5];
    const float* key_mem      = (const float*)d_in[6];
    const float* init_mem     = (const float*)d_in[7];
    const float* erase_w      = (const float*)d_in[8];
    const float* erase_b      = (const float*)d_in[9];
    const float* add_w        = (const float*)d_in[10];
    const float* add_b        = (const float*)d_in[11];
    const float* summary_w    = (const float*)d_in[12];
    const float* summary_b    = (const float*)d_in[13];
    const float* theta_w      = (const float*)d_in[14];
    const float* theta_b      = (const float*)d_in[15];
    const float* alpha_w      = (const float*)d_in[16];
    const float* alpha_b      = (const float*)d_in[17];
    const float* beta_w       = (const float*)d_in[18];
    const float* beta_b       = (const float*)d_in[19];
    float* out = (float*)d_out;

    build_q_tables<<<NQ, 64>>>(q_embed_w, key_mem, summary_w,
                               alpha_w, alpha_b, beta_w, beta_b);
    build_qr_tables<<<NQ, 128>>>(item_embed_w, value_proj_w, value_proj_b,
                                 erase_w, erase_b, add_w, add_b);
    scan_kernel<<<NB, 256>>>(questions, responses, init_mem);
    output_kernel<<<NPOS / CT, 128>>>(questions, summary_w, summary_b,
                                      theta_w, theta_b, out);
}